// round 3
// baseline (speedup 1.0000x reference)
#include <cuda_runtime.h>
#include <math.h>

#define N_    4096
#define V_    2
#define W_    32
#define H_    16
#define M_    512
#define EPSF  1e-6f
#define PIF   3.14159265358979323846f

// inputs:
// 0 points_normals (B,N,3)  1 points_albedo (B,N,3)  2 points_metallic (B,N,1)
// 3 points_smoothness (B,N,1)  4 viewing_dirs (B,N,V,3)  5 env_vis (B,N,M)
// 6 env_map (B,W,H,3)   output (B,N,V,3)

__global__ __launch_bounds__(128) void hdr_render_kernel(
    const float* __restrict__ normals,
    const float* __restrict__ albedo,
    const float* __restrict__ metallic,
    const float* __restrict__ smoothness,
    const float* __restrict__ viewdirs,
    const float* __restrict__ env_vis,
    const float* __restrict__ env_map,
    float* __restrict__ out)
{
    // Per-m tables, identical for all pairs.
    __shared__ float4 s_dir[M_];   // (lx, ly, lz, Li_R*sa)
    __shared__ float2 s_li[M_];    // (Li_G*sa, Li_B*sa)
    __shared__ float s_st[H_], s_ct[H_], s_sp[W_], s_cp[W_];

    const int tid = threadIdx.x;

    // 48 sincos per block instead of 1024.
    if (tid < H_) {
        const float theta = ((float)tid + 0.5f) * (1.0f / (float)H_) * PIF;
        sincosf(theta, &s_st[tid], &s_ct[tid]);
    } else if (tid < H_ + W_) {
        const int i = tid - H_;
        const float phi = ((float)i + 0.5f) * (1.0f / (float)W_) * (2.0f * PIF) + 0.5f * PIF;
        sincosf(phi, &s_sp[i], &s_cp[i]);
    }
    __syncthreads();

    const float K_SA = (PIF / (float)H_) * (2.0f * PIF / (float)W_);
    #pragma unroll
    for (int m = tid; m < M_; m += 128) {
        const int j = m >> 5;          // theta index (H)
        const int i = m & (W_ - 1);    // phi index (W)
        const float st = s_st[j], ct = s_ct[j];
        const float sp = s_sp[i], cp = s_cp[i];
        const float sa = st * K_SA;
        // exact texel fetch (bilinear degenerates): Li = env_map[0, i, j, :]
        const float* e = env_map + (i * H_ + j) * 3;
        s_dir[m] = make_float4(st * cp, ct, -st * sp, e[0] * sa);
        s_li[m]  = make_float2(e[1] * sa, e[2] * sa);
    }
    __syncthreads();

    const int gwarp = (blockIdx.x * 128 + tid) >> 5;  // pair = n*V + vi (grid exact)
    const int lane  = tid & 31;
    const int n  = gwarp >> 1;

    // ---- warp-invariant setup ----
    float nx = normals[n * 3 + 0];
    float ny = normals[n * 3 + 1];
    float nz = normals[n * 3 + 2];
    {
        const float inv = rsqrtf(fmaxf(fmaf(nx, nx, fmaf(ny, ny, nz * nz)), 1e-24f));
        nx *= inv; ny *= inv; nz *= inv;
    }
    const float* vd = viewdirs + gwarp * 3;
    float vx = vd[0], vy = vd[1], vz = vd[2];
    {
        const float inv = rsqrtf(fmaxf(fmaf(vx, vx, fmaf(vy, vy, vz * vz)), 1e-24f));
        vx *= inv; vy *= inv; vz *= inv;
    }

    const float met    = metallic[n];
    const float rough  = 1.0f - smoothness[n];
    const float alpha  = rough * rough;
    const float alpha2 = alpha * alpha;
    const float a2m1   = alpha2 - 1.0f;
    const float k      = 0.5f * alpha;
    const float omk    = 1.0f - k;
    const float k_eps  = k + EPSF;

    const float ar = albedo[n * 3 + 0];
    const float ag = albedo[n * 3 + 1];
    const float ab = albedo[n * 3 + 2];
    const float f0r = fmaf(ar - 0.04f, met, 0.04f);
    const float f0g = fmaf(ag - 0.04f, met, 0.04f);
    const float f0b = fmaf(ab - 0.04f, met, 0.04f);
    const float omf0r = 1.0f - f0r;
    const float omf0g = 1.0f - f0g;
    const float omf0b = 1.0f - f0b;

    const float NdotV   = fmaxf(fmaf(nx, vx, fmaf(ny, vy, nz * vz)), EPSF);
    const float Gv      = NdotV / fmaf(NdotV, omk, k_eps);
    const float a2Gv    = alpha2 * Gv;
    const float fourNdV = 4.0f * NdotV;

    const float dcom = (1.0f - met) * (1.0f / PIF);
    const float dR = dcom * ar;
    const float dG = dcom * ag;
    const float dB = dcom * ab;

    const float* __restrict__ vis = env_vis + n * M_;

    float accR = 0.0f, accG = 0.0f, accB = 0.0f;

    #pragma unroll 8
    for (int m = lane; m < M_; m += 32) {
        const float4 ds = s_dir[m];
        const float2 lg = s_li[m];
        const float lx = ds.x, ly = ds.y, lz = ds.z;

        // explicit half vector — tracks reference rounding in the l ~ -v region
        const float hx = vx + lx, hy = vy + ly, hz = vz + lz;
        const float hinv = rsqrtf(fmaxf(fmaf(hx, hx, fmaf(hy, hy, hz * hz)), 1e-24f));

        const float nl    = fmaf(lx, nx, fmaf(ly, ny, lz * nz));
        const float NdotL = fmaxf(nl, EPSF);
        const float NdotH = fmaxf(fmaf(nx, hx, fmaf(ny, hy, nz * hz)) * hinv, 0.0f);
        const float VdotH = fmaxf(fmaf(lx, hx, fmaf(ly, hy, lz * hz)) * hinv, 0.0f);

        const float t  = 1.0f - fminf(VdotH, 1.0f);
        const float t2 = t * t;
        const float p5 = t2 * t2 * t;

        const float dd   = fmaf(NdotH * NdotH, a2m1, 1.0f);
        const float den1 = fmaf(PIF * dd, dd, EPSF);
        const float den2 = fmaf(NdotL, omk, k_eps);
        const float den3 = fmaf(fourNdV, NdotL, EPSF);
        const float s    = __fdividef(a2Gv * NdotL, den1 * (den2 * den3));

        const float w = vis[m] * NdotL;      // sa pre-folded into table

        const float FrR = fmaf(omf0r, p5, f0r);
        const float FrG = fmaf(omf0g, p5, f0g);
        const float FrB = fmaf(omf0b, p5, f0b);

        accR = fmaf(fmaf(FrR, s - dR, dR), ds.w * w, accR);
        accG = fmaf(fmaf(FrG, s - dG, dG), lg.x * w, accG);
        accB = fmaf(fmaf(FrB, s - dB, dB), lg.y * w, accB);
    }

    #pragma unroll
    for (int off = 16; off > 0; off >>= 1) {
        accR += __shfl_down_sync(0xffffffffu, accR, off);
        accG += __shfl_down_sync(0xffffffffu, accG, off);
        accB += __shfl_down_sync(0xffffffffu, accB, off);
    }

    if (lane == 0) {
        float* o = out + gwarp * 3;
        o[0] = accR;
        o[1] = accG;
        o[2] = accB;
    }
}

extern "C" void kernel_launch(void* const* d_in, const int* in_sizes, int n_in,
                              void* d_out, int out_size)
{
    const float* normals    = (const float*)d_in[0];
    const float* albedo     = (const float*)d_in[1];
    const float* metallic   = (const float*)d_in[2];
    const float* smoothness = (const float*)d_in[3];
    const float* viewdirs   = (const float*)d_in[4];
    const float* env_vis    = (const float*)d_in[5];
    const float* env_map    = (const float*)d_in[6];
    float* out = (float*)d_out;

    const int pairs   = N_ * V_;           // 8192 (one warp each)
    const int threads = 128;               // 4 warps/block
    const int blocks  = pairs / 4;         // 2048

    hdr_render_kernel<<<blocks, threads>>>(normals, albedo, metallic, smoothness,
                                           viewdirs, env_vis, env_map, out);
}

// round 4
// speedup vs baseline: 1.6774x; 1.6774x over previous
#include <cuda_runtime.h>
#include <math.h>

#define N_    4096
#define V_    2
#define W_    32
#define H_    16
#define M_    512
#define EPSF  1e-6f
#define PIF   3.14159265358979323846f

// inputs:
// 0 points_normals (B,N,3)  1 points_albedo (B,N,3)  2 points_metallic (B,N,1)
// 3 points_smoothness (B,N,1)  4 viewing_dirs (B,N,V,3)  5 env_vis (B,N,M)
// 6 env_map (B,W,H,3)   output (B,N,V,3)

// Precomputed per-m tables (filled once per launch by prep kernel).
__device__ float4 g_tab_dir[M_];   // (lx, ly, lz, Li_R*sa)
__device__ float2 g_tab_li[M_];    // (Li_G*sa, Li_B*sa)

__global__ void hdr_prep_kernel(const float* __restrict__ env_map)
{
    const int m = blockIdx.x * blockDim.x + threadIdx.x;
    if (m >= M_) return;
    const int j = m >> 5;          // theta index (H)
    const int i = m & (W_ - 1);    // phi index (W)
    const float theta = ((float)j + 0.5f) * (1.0f / (float)H_) * PIF;
    const float phi   = ((float)i + 0.5f) * (1.0f / (float)W_) * (2.0f * PIF) + 0.5f * PIF;
    float st, ct, sp, cp;
    sincosf(theta, &st, &ct);
    sincosf(phi,   &sp, &cp);
    const float sa = st * ((PIF / (float)H_) * (2.0f * PIF / (float)W_));
    // bilinear grid_sample degenerates to exact texel fetch: Li = env_map[0, i, j, :]
    const float* e = env_map + (i * H_ + j) * 3;
    g_tab_dir[m] = make_float4(st * cp, ct, -st * sp, e[0] * sa);
    g_tab_li[m]  = make_float2(e[1] * sa, e[2] * sa);
}

__global__ __launch_bounds__(256) void hdr_render_kernel(
    const float* __restrict__ normals,
    const float* __restrict__ albedo,
    const float* __restrict__ metallic,
    const float* __restrict__ smoothness,
    const float* __restrict__ viewdirs,
    const float* __restrict__ env_vis,
    float* __restrict__ out)
{
    __shared__ float4 s_dir[M_];
    __shared__ float2 s_li[M_];

    const int tid = threadIdx.x;

    // Coalesced 12 KB copy from L2-resident global tables.
    #pragma unroll
    for (int m = tid; m < M_; m += 256) {
        s_dir[m] = g_tab_dir[m];
        s_li[m]  = g_tab_li[m];
    }
    __syncthreads();

    const int gwarp = (blockIdx.x * 256 + tid) >> 5;  // pair = n*V + vi (grid exact)
    const int lane  = tid & 31;
    const int n  = gwarp >> 1;

    // ---- warp-invariant setup ----
    float nx = normals[n * 3 + 0];
    float ny = normals[n * 3 + 1];
    float nz = normals[n * 3 + 2];
    {
        const float inv = rsqrtf(fmaxf(fmaf(nx, nx, fmaf(ny, ny, nz * nz)), 1e-24f));
        nx *= inv; ny *= inv; nz *= inv;
    }
    const float* vd = viewdirs + gwarp * 3;
    float vx = vd[0], vy = vd[1], vz = vd[2];
    {
        const float inv = rsqrtf(fmaxf(fmaf(vx, vx, fmaf(vy, vy, vz * vz)), 1e-24f));
        vx *= inv; vy *= inv; vz *= inv;
    }

    const float met    = metallic[n];
    const float rough  = 1.0f - smoothness[n];
    const float alpha  = rough * rough;
    const float alpha2 = alpha * alpha;
    const float a2m1   = alpha2 - 1.0f;
    const float k      = 0.5f * alpha;
    const float omk    = 1.0f - k;
    const float k_eps  = k + EPSF;

    const float ar = albedo[n * 3 + 0];
    const float ag = albedo[n * 3 + 1];
    const float ab = albedo[n * 3 + 2];
    const float f0r = fmaf(ar - 0.04f, met, 0.04f);
    const float f0g = fmaf(ag - 0.04f, met, 0.04f);
    const float f0b = fmaf(ab - 0.04f, met, 0.04f);
    const float omf0r = 1.0f - f0r;
    const float omf0g = 1.0f - f0g;
    const float omf0b = 1.0f - f0b;

    const float NdotV   = fmaxf(fmaf(nx, vx, fmaf(ny, vy, nz * vz)), EPSF);
    const float Gv      = NdotV / fmaf(NdotV, omk, k_eps);
    const float a2Gv    = alpha2 * Gv;
    const float fourNdV = 4.0f * NdotV;

    const float dcom = (1.0f - met) * (1.0f / PIF);
    const float dR = dcom * ar;
    const float dG = dcom * ag;
    const float dB = dcom * ab;

    const float* __restrict__ vis = env_vis + n * M_;

    float accR = 0.0f, accG = 0.0f, accB = 0.0f;

    #pragma unroll 8
    for (int m = lane; m < M_; m += 32) {
        const float4 ds = s_dir[m];
        const float2 lg = s_li[m];
        const float lx = ds.x, ly = ds.y, lz = ds.z;

        // explicit half vector — tracks reference rounding in the l ~ -v region
        const float hx = vx + lx, hy = vy + ly, hz = vz + lz;
        const float hinv = rsqrtf(fmaxf(fmaf(hx, hx, fmaf(hy, hy, hz * hz)), 1e-24f));

        const float nl    = fmaf(lx, nx, fmaf(ly, ny, lz * nz));
        const float NdotL = fmaxf(nl, EPSF);
        const float NdotH = fmaxf(fmaf(nx, hx, fmaf(ny, hy, nz * hz)) * hinv, 0.0f);
        const float VdotH = fmaxf(fmaf(lx, hx, fmaf(ly, hy, lz * hz)) * hinv, 0.0f);

        const float t  = 1.0f - fminf(VdotH, 1.0f);
        const float t2 = t * t;
        const float p5 = t2 * t2 * t;

        const float dd   = fmaf(NdotH * NdotH, a2m1, 1.0f);
        const float den1 = fmaf(PIF * dd, dd, EPSF);
        const float den2 = fmaf(NdotL, omk, k_eps);
        const float den3 = fmaf(fourNdV, NdotL, EPSF);
        const float s    = __fdividef(a2Gv * NdotL, den1 * (den2 * den3));

        const float w = vis[m] * NdotL;      // sa pre-folded into table

        const float FrR = fmaf(omf0r, p5, f0r);
        const float FrG = fmaf(omf0g, p5, f0g);
        const float FrB = fmaf(omf0b, p5, f0b);

        accR = fmaf(fmaf(FrR, s - dR, dR), ds.w * w, accR);
        accG = fmaf(fmaf(FrG, s - dG, dG), lg.x * w, accG);
        accB = fmaf(fmaf(FrB, s - dB, dB), lg.y * w, accB);
    }

    #pragma unroll
    for (int off = 16; off > 0; off >>= 1) {
        accR += __shfl_down_sync(0xffffffffu, accR, off);
        accG += __shfl_down_sync(0xffffffffu, accG, off);
        accB += __shfl_down_sync(0xffffffffu, accB, off);
    }

    if (lane == 0) {
        float* o = out + gwarp * 3;
        o[0] = accR;
        o[1] = accG;
        o[2] = accB;
    }
}

extern "C" void kernel_launch(void* const* d_in, const int* in_sizes, int n_in,
                              void* d_out, int out_size)
{
    const float* normals    = (const float*)d_in[0];
    const float* albedo     = (const float*)d_in[1];
    const float* metallic   = (const float*)d_in[2];
    const float* smoothness = (const float*)d_in[3];
    const float* viewdirs   = (const float*)d_in[4];
    const float* env_vis    = (const float*)d_in[5];
    const float* env_map    = (const float*)d_in[6];
    float* out = (float*)d_out;

    hdr_prep_kernel<<<2, 256>>>(env_map);

    const int pairs   = N_ * V_;           // 8192 (one warp each)
    const int threads = 256;               // 8 warps/block
    const int blocks  = pairs * 32 / threads;  // 1024

    hdr_render_kernel<<<blocks, threads>>>(normals, albedo, metallic, smoothness,
                                           viewdirs, env_vis, out);
}